// round 15
// baseline (speedup 1.0000x reference)
#include <cuda_runtime.h>
#include <cuda_fp16.h>
#include <cstdint>

// SelfConnectionIntro via baseline-PTX HMMA (mma.sync m16n8k16 f16):
// out_l[z,w,k] = alpha * sum_v opr[z,v] * (x_l[:,:,k] @ W_l[:,v,:])[z,w]
// R15 = R14 (v-outer / ks-inner, per-v fp32 opr epilogue) with deeper
// software pipelining: B fragments prefetched TWO steps ahead (covers L2
// latency ~250cyc), A fragments double-buffered one ks ahead. Geometry,
// layouts and epilogue identical to R14.

__device__ __forceinline__ uint32_t smem_u32(const void* p) {
    uint32_t a;
    asm("{ .reg .u64 t; cvta.to.shared.u64 t, %1; cvt.u32.u64 %0, t; }" : "=r"(a) : "l"(p));
    return a;
}
__device__ __forceinline__ void ldmat_x4(uint32_t r[4], uint32_t a) {
    asm volatile("ldmatrix.sync.aligned.m8n8.x4.shared.b16 {%0,%1,%2,%3}, [%4];"
                 : "=r"(r[0]), "=r"(r[1]), "=r"(r[2]), "=r"(r[3]) : "r"(a));
}
__device__ __forceinline__ void mma16816(float d[4], const uint32_t a[4],
                                         uint32_t b0, uint32_t b1) {
    asm volatile("mma.sync.aligned.m16n8k16.row.col.f32.f16.f16.f32 "
                 "{%0,%1,%2,%3},{%4,%5,%6,%7},{%8,%9},{%0,%1,%2,%3};"
                 : "+f"(d[0]), "+f"(d[1]), "+f"(d[2]), "+f"(d[3])
                 : "r"(a[0]), "r"(a[1]), "r"(a[2]), "r"(a[3]), "r"(b0), "r"(b1));
}
__device__ __forceinline__ void mma16816_z(float d[4], const uint32_t a[4],
                                           uint32_t b0, uint32_t b1) {
    asm volatile("mma.sync.aligned.m16n8k16.row.col.f32.f16.f16.f32 "
                 "{%0,%1,%2,%3},{%4,%5,%6,%7},{%8,%9},{%10,%11,%12,%13};"
                 : "=f"(d[0]), "=f"(d[1]), "=f"(d[2]), "=f"(d[3])
                 : "r"(a[0]), "r"(a[1]), "r"(a[2]), "r"(a[3]), "r"(b0), "r"(b1),
                   "f"(0.0f), "f"(0.0f), "f"(0.0f), "f"(0.0f));
}

// B images: [v(16)][ks][nb][lane(32)] of uint2 = {b_r0, b_r1} (fp16x2 each).
__device__ uint2 BIMG0[16 * 8 * 16 * 32];
__device__ uint2 BIMG1[16 * 4 *  8 * 32];
__device__ uint2 BIMG2[16 * 2 *  4 * 32];

// W layout [U][16][NTOT]. HMMA B frag (k16 x n8): lane t, reg r, half hh:
//   u = ks*16 + 2*(t&3) + hh + r*8 ; n = nb*8 + t/4 ; value = W[u][v][n].
template<int U, int NTOT>
__global__ void prepB(const float* __restrict__ W, uint2* __restrict__ dst) {
    constexpr int KS = U / 16, NBT = NTOT / 8;
    const int total = 16 * KS * NBT * 32;
    for (int i = blockIdx.x * blockDim.x + threadIdx.x; i < total;
         i += gridDim.x * blockDim.x) {
        int lane = i & 31, r1 = i >> 5;
        int nb = r1 % NBT; r1 /= NBT;
        int ks = r1 % KS;  r1 /= KS;
        int v = r1;
        int n = nb * 8 + (lane >> 2);
        uint32_t wr[2];
#pragma unroll
        for (int r = 0; r < 2; r++) {
            uint32_t word = 0;
#pragma unroll
            for (int hh = 0; hh < 2; hh++) {
                int u = ks * 16 + 2 * (lane & 3) + hh + r * 8;
                __half h = __float2half_rn(W[((size_t)u * 16 + v) * NTOT + n]);
                word |= (uint32_t)(*(uint16_t*)&h) << (hh * 16);
            }
            wr[r] = word;
        }
        dst[i] = make_uint2(wr[0], wr[1]);
    }
}

// Main kernel. M-rows = stacked (z,k): r = z*D + k, total rows Z*D.
// CTA = 128 rows x NT channels (blockIdx.z selects NT slice of NTOT).
template<int U, int NTOT, int NT, int D, int WM, int WN, int MW, int NBW>
__global__ __launch_bounds__(WM * WN * 32, 2)
void fctp_hmma(const float* __restrict__ x, const float* __restrict__ opr,
               const uint2* __restrict__ Bimg, float* __restrict__ out,
               int Z, int xoff, float alpha)
{
    constexpr int KS = U / 16, NBT = NTOT / 8, RS = U + 8;
    constexpr int NTH = WM * WN * 32;
    constexpr int XB = 128 * RS * 2;
    constexpr int AR = MW * NBW * 4;
    constexpr int UD = U * D;
    constexpr int SMAX = 16 * KS;              // total steps
    static_assert((KS & 1) == 0, "KS must be even for A parity");

    extern __shared__ char smraw[];
    __half* xs  = (__half*)smraw;                          // [128][RS] fp16
    float*  ops = (float*)(smraw + XB);                    // [128][17]

    const int tid = threadIdx.x, lane = tid & 31, wid = tid >> 5;
    const int wm = wid % WM, wn = wid / WM;
    const int moff = wm * MW * 16;
    const int nb0 = blockIdx.z * (NT / 8) + wn * NBW;
    const int rbase = blockIdx.x * 128;
    const int ZD = Z * D;

    // Tail tiles: zero-fill A so invalid rows contribute 0.
    if (rbase + 128 > ZD) {
        for (int e = tid; e < 128 * RS / 2; e += NTH)
            ((uint32_t*)xs)[e] = 0u;
        __syncthreads();
    }

    // Stage x fp16: coalesced float4 over contiguous per-z chunks, transpose-scatter.
    {
        const int z_lo = rbase / D;
        const int nchunk = (rbase + 127) / D - z_lo + 1;
        const int total4 = nchunk * (UD / 4);
        for (int q = tid; q < total4; q += NTH) {
            int f = q * 4;
            int zc = f / UD;
            int p  = f - zc * UD;
            int z  = z_lo + zc;
            if (z < Z) {
                float4 val = *(const float4*)(x + (size_t)z * 480 + xoff + p);
                float vv[4] = {val.x, val.y, val.z, val.w};
#pragma unroll
                for (int i = 0; i < 4; i++) {
                    int pi = p + i;
                    int u  = pi / D;
                    int k  = pi - u * D;
                    int m  = z * D + k - rbase;
                    if (m >= 0 && m < 128)
                        xs[m * RS + u] = __float2half_rn(vv[i]);
                }
            }
        }
    }
    for (int e = tid; e < 128 * 16; e += NTH) {
        int m = e >> 4, v = e & 15;
        int z = (rbase + m) / D;
        ops[m * 17 + v] = (z < Z) ? opr[(size_t)z * 16 + v] : 0.0f;
    }
    __syncthreads();

    const uint32_t xB = smem_u32(xs);
    const uint32_t aLane = (uint32_t)(moff + (lane & 15)) * (RS * 2) + ((lane >> 4) << 4);
    const uint2* pB = Bimg + (size_t)nb0 * 32 + lane;   // + s*KSTR + j*32
    constexpr size_t KSTR = (size_t)NBT * 32;

    float acc[AR];
#pragma unroll
    for (int i = 0; i < AR; i++) acc[i] = 0.0f;

    uint2 Q[2][NBW];
    uint32_t A[2][MW][4];

    // Prime: B steps 0 and 1; A for ks=0.
#pragma unroll
    for (int j = 0; j < NBW; j++) Q[0][j] = pB[j * 32];
#pragma unroll
    for (int j = 0; j < NBW; j++) Q[1][j] = (pB + KSTR)[j * 32];
#pragma unroll
    for (int mb = 0; mb < MW; mb++)
        ldmat_x4(A[0][mb], xB + aLane + mb * 16 * RS * 2);

#pragma unroll 1
    for (int v = 0; v < 16; v++) {
        float d[AR];

#pragma unroll
        for (int ks = 0; ks < KS; ks++) {
            const int s = v * KS + ks;
            const int ab = ks & 1, sb = s & 1;

            // MMA: consume A[ab], Q[sb]; accumulate into d across ks.
#pragma unroll
            for (int mb = 0; mb < MW; mb++)
#pragma unroll
                for (int j = 0; j < NBW; j++) {
                    float* dd = &d[(mb * NBW + j) * 4];
                    if (ks == 0)
                        mma16816_z(dd, A[ab][mb], Q[sb][j].x, Q[sb][j].y);
                    else
                        mma16816(dd, A[ab][mb], Q[sb][j].x, Q[sb][j].y);
                }

            // A prefetch: ks+1 (mod KS; KS even -> parity consistent across v).
            {
                const int nks = (ks + 1 == KS) ? 0 : ks + 1;
#pragma unroll
                for (int mb = 0; mb < MW; mb++)
                    ldmat_x4(A[nks & 1][mb],
                             xB + aLane + nks * 32 + mb * 16 * RS * 2);
            }
            // B prefetch: step s+2 into the buffer just consumed (Q[sb]).
            if (s + 2 < SMAX) {
                const uint2* p = pB + (size_t)(s + 2) * KSTR;
#pragma unroll
                for (int j = 0; j < NBW; j++) Q[sb][j] = p[j * 32];
            }
        }

        // epilogue once per v: acc += opr[row,v] * d
#pragma unroll
        for (int mb = 0; mb < MW; mb++) {
            float o0 = ops[(moff + mb * 16 + (lane >> 2)) * 17 + v];
            float o1 = ops[(moff + mb * 16 + (lane >> 2) + 8) * 17 + v];
#pragma unroll
            for (int j = 0; j < NBW; j++) {
                float* dd = &d[(mb * NBW + j) * 4];
                float* aa = &acc[(mb * NBW + j) * 4];
                aa[0] = fmaf(o0, dd[0], aa[0]);
                aa[1] = fmaf(o0, dd[1], aa[1]);
                aa[2] = fmaf(o1, dd[2], aa[2]);
                aa[3] = fmaf(o1, dd[3], aa[3]);
            }
        }
    }

    // store: row R = z*D + k
#pragma unroll
    for (int mb = 0; mb < MW; mb++) {
        int R = rbase + moff + mb * 16 + (lane >> 2);
#pragma unroll
        for (int j = 0; j < NBW; j++) {
            int n = (nb0 + j) * 8 + 2 * (lane & 3);
            float* aa = &acc[(mb * NBW + j) * 4];
            if (D == 1) {
                if (R < Z)
                    *(float2*)&out[(size_t)R * 480 + xoff + n] =
                        make_float2(alpha * aa[0], alpha * aa[1]);
                if (R + 8 < Z)
                    *(float2*)&out[(size_t)(R + 8) * 480 + xoff + n] =
                        make_float2(alpha * aa[2], alpha * aa[3]);
            } else {
                if (R < ZD) {
                    int z = R / D, k = R - z * D;
                    out[(size_t)z * 480 + xoff + n * D + k]       = alpha * aa[0];
                    out[(size_t)z * 480 + xoff + (n + 1) * D + k] = alpha * aa[1];
                }
                int R2 = R + 8;
                if (R2 < ZD) {
                    int z = R2 / D, k = R2 - z * D;
                    out[(size_t)z * 480 + xoff + n * D + k]       = alpha * aa[2];
                    out[(size_t)z * 480 + xoff + (n + 1) * D + k] = alpha * aa[3];
                }
            }
        }
    }
}

extern "C" void kernel_launch(void* const* d_in, const int* in_sizes, int n_in,
                              void* d_out, int out_size)
{
    const float* x   = (const float*)d_in[0];
    const float* opr = (const float*)d_in[1];
    const float* w0  = (const float*)d_in[2];
    const float* w1  = (const float*)d_in[3];
    const float* w2  = (const float*)d_in[4];
    float* out = (float*)d_out;

    const int Z = in_sizes[1] / 16;

    const float a0 = 0.022097086912079608f;  // 1/sqrt(128*16)
    const float a1 = 0.03125f;               // 1/sqrt(64*16)
    const float a2 = 0.044194173824159216f;  // 1/sqrt(32*16)

    void *p0, *p1, *p2;
    cudaGetSymbolAddress(&p0, BIMG0);
    cudaGetSymbolAddress(&p1, BIMG1);
    cudaGetSymbolAddress(&p2, BIMG2);

    prepB<128, 128><<<128, 256>>>(w0, (uint2*)p0);
    prepB< 64,  64><<< 32, 256>>>(w1, (uint2*)p1);
    prepB< 32,  32><<<  8, 256>>>(w2, (uint2*)p2);

    // path0: U=128, N=128, D=1; NT=64 (grid.z=2); 256 thr, warps 4x2, m32xn32
    {
        constexpr int SM = 128 * 136 * 2 + 128 * 17 * 4;  // 43520
        cudaFuncSetAttribute(fctp_hmma<128, 128, 64, 1, 4, 2, 2, 4>,
                             cudaFuncAttributeMaxDynamicSharedMemorySize, SM);
        dim3 grid((Z + 127) / 128, 1, 2);
        fctp_hmma<128, 128, 64, 1, 4, 2, 2, 4><<<grid, 256, SM>>>(
            x, opr, (const uint2*)p0, out, Z, 0, a0);
    }
    // path1: U=64, N=64, D=3; NT=64; 256 thr, warps 4x2, m32xn32
    {
        constexpr int SM = 128 * 72 * 2 + 128 * 17 * 4;   // 27136
        cudaFuncSetAttribute(fctp_hmma<64, 64, 64, 3, 4, 2, 2, 4>,
                             cudaFuncAttributeMaxDynamicSharedMemorySize, SM);
        dim3 grid((3 * Z + 127) / 128, 1, 1);
        fctp_hmma<64, 64, 64, 3, 4, 2, 2, 4><<<grid, 256, SM>>>(
            x, opr, (const uint2*)p1, out, Z, 128, a1);
    }
    // path2: U=32, N=32, D=5; NT=32; 256 thr, warps 4x2, m32xn16
    {
        constexpr int SM = 128 * 40 * 2 + 128 * 17 * 4;   // 18944
        cudaFuncSetAttribute(fctp_hmma<32, 32, 32, 5, 4, 2, 2, 2>,
                             cudaFuncAttributeMaxDynamicSharedMemorySize, SM);
        dim3 grid((5 * Z + 127) / 128, 1, 1);
        fctp_hmma<32, 32, 32, 5, 4, 2, 2, 2><<<grid, 256, SM>>>(
            x, opr, (const uint2*)p2, out, Z, 320, a2);
    }
}

// round 16
// speedup vs baseline: 1.1379x; 1.1379x over previous
#include <cuda_runtime.h>
#include <cuda_fp16.h>
#include <cstdint>

// SelfConnectionIntro via baseline-PTX HMMA (mma.sync m16n8k16 f16):
// out_l[z,w,k] = alpha * sum_v opr[z,v] * (x_l[:,:,k] @ W_l[:,v,:])[z,w]
// R16 = R14 (best: v-outer / ks-inner, d accumulates over K in the MMA chain,
// per-v fp32 opr epilogue) with three frictions removed:
//  1) B image packed as uint4 (two n8-blocks per LDG.128 -> half the LDG issues)
//  2) LDSM(A, current ks) issued BEFORE the B-prefetch LDGs in each step
//  3) ops (opr scales) preloaded into registers before each v's ks loop

__device__ __forceinline__ uint32_t smem_u32(const void* p) {
    uint32_t a;
    asm("{ .reg .u64 t; cvta.to.shared.u64 t, %1; cvt.u32.u64 %0, t; }" : "=r"(a) : "l"(p));
    return a;
}
__device__ __forceinline__ void ldmat_x4(uint32_t r[4], uint32_t a) {
    asm volatile("ldmatrix.sync.aligned.m8n8.x4.shared.b16 {%0,%1,%2,%3}, [%4];"
                 : "=r"(r[0]), "=r"(r[1]), "=r"(r[2]), "=r"(r[3]) : "r"(a));
}
__device__ __forceinline__ void mma16816(float d[4], const uint32_t a[4],
                                         uint32_t b0, uint32_t b1) {
    asm volatile("mma.sync.aligned.m16n8k16.row.col.f32.f16.f16.f32 "
                 "{%0,%1,%2,%3},{%4,%5,%6,%7},{%8,%9},{%0,%1,%2,%3};"
                 : "+f"(d[0]), "+f"(d[1]), "+f"(d[2]), "+f"(d[3])
                 : "r"(a[0]), "r"(a[1]), "r"(a[2]), "r"(a[3]), "r"(b0), "r"(b1));
}
__device__ __forceinline__ void mma16816_z(float d[4], const uint32_t a[4],
                                           uint32_t b0, uint32_t b1) {
    asm volatile("mma.sync.aligned.m16n8k16.row.col.f32.f16.f16.f32 "
                 "{%0,%1,%2,%3},{%4,%5,%6,%7},{%8,%9},{%10,%11,%12,%13};"
                 : "=f"(d[0]), "=f"(d[1]), "=f"(d[2]), "=f"(d[3])
                 : "r"(a[0]), "r"(a[1]), "r"(a[2]), "r"(a[3]), "r"(b0), "r"(b1),
                   "f"(0.0f), "f"(0.0f), "f"(0.0f), "f"(0.0f));
}

// B images: [v(16)][ks][nbpair][lane(32)] of uint4 =
//   {b(nb=2p,r0), b(2p,r1), b(2p+1,r0), b(2p+1,r1)}  (each fp16x2)
__device__ uint4 BIMG0[16 * 8 * 8 * 32];   // path0 U=128 N=128
__device__ uint4 BIMG1[16 * 4 * 4 * 32];   // path1 U=64  N=64
__device__ uint4 BIMG2[16 * 2 * 2 * 32];   // path2 U=32  N=32

// W layout [U][16][NTOT]. HMMA B frag (k16 x n8): lane t, reg r, half hh:
//   u = ks*16 + 2*(t&3) + hh + r*8 ; n = nb*8 + t/4 ; value = W[u][v][n].
template<int U, int NTOT>
__global__ void prepB(const float* __restrict__ W, uint4* __restrict__ dst) {
    constexpr int KS = U / 16, NPT = NTOT / 16;   // nb-pairs total
    const int total = 16 * KS * NPT * 32;
    for (int i = blockIdx.x * blockDim.x + threadIdx.x; i < total;
         i += gridDim.x * blockDim.x) {
        int lane = i & 31, r1 = i >> 5;
        int np = r1 % NPT; r1 /= NPT;
        int ks = r1 % KS;  r1 /= KS;
        int v = r1;
        uint32_t w4[4];
#pragma unroll
        for (int half = 0; half < 2; half++) {     // nb = 2*np + half
            int n = (2 * np + half) * 8 + (lane >> 2);
#pragma unroll
            for (int r = 0; r < 2; r++) {
                uint32_t word = 0;
#pragma unroll
                for (int hh = 0; hh < 2; hh++) {
                    int u = ks * 16 + 2 * (lane & 3) + hh + r * 8;
                    __half h = __float2half_rn(W[((size_t)u * 16 + v) * NTOT + n]);
                    word |= (uint32_t)(*(uint16_t*)&h) << (hh * 16);
                }
                w4[half * 2 + r] = word;
            }
        }
        dst[i] = make_uint4(w4[0], w4[1], w4[2], w4[3]);
    }
}

// Main kernel. M-rows = stacked (z,k): r = z*D + k, total rows Z*D.
// CTA = 128 rows x NT channels (blockIdx.z selects NT slice of NTOT).
template<int U, int NTOT, int NT, int D, int WM, int WN, int MW, int NBW>
__global__ __launch_bounds__(WM * WN * 32, 2)
void fctp_hmma(const float* __restrict__ x, const float* __restrict__ opr,
               const uint4* __restrict__ Bimg, float* __restrict__ out,
               int Z, int xoff, float alpha)
{
    constexpr int KS = U / 16, RS = U + 8;
    constexpr int NPT = NTOT / 16;             // nb-pairs total
    constexpr int NPW = NBW / 2;               // nb-pairs per warp
    constexpr int NTH = WM * WN * 32;
    constexpr int XB = 128 * RS * 2;
    constexpr int AR = MW * NBW * 4;
    constexpr int UD = U * D;
    static_assert(NBW % 2 == 0, "NBW even for uint4 B packing");

    extern __shared__ char smraw[];
    __half* xs  = (__half*)smraw;                          // [128][RS] fp16
    float*  ops = (float*)(smraw + XB);                    // [128][17]

    const int tid = threadIdx.x, lane = tid & 31, wid = tid >> 5;
    const int wm = wid % WM, wn = wid / WM;
    const int moff = wm * MW * 16;
    const int nb0 = blockIdx.z * (NT / 8) + wn * NBW;      // even by construction
    const int rbase = blockIdx.x * 128;
    const int ZD = Z * D;

    // Tail tiles: zero-fill A so invalid rows contribute 0.
    if (rbase + 128 > ZD) {
        for (int e = tid; e < 128 * RS / 2; e += NTH)
            ((uint32_t*)xs)[e] = 0u;
        __syncthreads();
    }

    // Stage x fp16: coalesced float4 over contiguous per-z chunks, transpose-scatter.
    {
        const int z_lo = rbase / D;
        const int nchunk = (rbase + 127) / D - z_lo + 1;
        const int total4 = nchunk * (UD / 4);
        for (int q = tid; q < total4; q += NTH) {
            int f = q * 4;
            int zc = f / UD;
            int p  = f - zc * UD;
            int z  = z_lo + zc;
            if (z < Z) {
                float4 val = *(const float4*)(x + (size_t)z * 480 + xoff + p);
                float vv[4] = {val.x, val.y, val.z, val.w};
#pragma unroll
                for (int i = 0; i < 4; i++) {
                    int pi = p + i;
                    int u  = pi / D;
                    int k  = pi - u * D;
                    int m  = z * D + k - rbase;
                    if (m >= 0 && m < 128)
                        xs[m * RS + u] = __float2half_rn(vv[i]);
                }
            }
        }
    }
    for (int e = tid; e < 128 * 16; e += NTH) {
        int m = e >> 4, v = e & 15;
        int z = (rbase + m) / D;
        ops[m * 17 + v] = (z < Z) ? opr[(size_t)z * 16 + v] : 0.0f;
    }
    __syncthreads();

    const uint32_t xB = smem_u32(xs);
    const uint32_t aLane = (uint32_t)(moff + (lane & 15)) * (RS * 2) + ((lane >> 4) << 4);
    const uint4* pB = Bimg + (size_t)(nb0 / 2) * 32 + lane;   // + s*K4STR + p*32
    constexpr size_t K4STR = (size_t)NPT * 32;                 // per-(v,ks) stride

    float acc[AR];
#pragma unroll
    for (int i = 0; i < AR; i++) acc[i] = 0.0f;

    uint4 Q[2][NPW];
#pragma unroll
    for (int p = 0; p < NPW; p++) Q[0][p] = pB[p * 32];    // (v=0, ks=0)

#pragma unroll 1
    for (int v = 0; v < 16; v++) {
        float d[AR];

        // preload opr scales for this v (LDS hidden under the MMA block)
        float o0[MW], o1[MW];
#pragma unroll
        for (int mb = 0; mb < MW; mb++) {
            o0[mb] = ops[(moff + mb * 16 + (lane >> 2)) * 17 + v];
            o1[mb] = ops[(moff + mb * 16 + (lane >> 2) + 8) * 17 + v];
        }

#pragma unroll
        for (int ks = 0; ks < KS; ks++) {
            // A frags for this ks (issued first: gains cover from the LDGs below)
            uint32_t A[MW][4];
            uint32_t ba = xB + aLane + ks * 32;
#pragma unroll
            for (int mb = 0; mb < MW; mb++)
                ldmat_x4(A[mb], ba + mb * 16 * RS * 2);

            // prefetch next B frag group: (v, ks+1) or (v+1, 0); parity (ks+1)&1.
            {
                int nidx = (ks + 1 < KS) ? (v * KS + ks + 1) : ((v + 1) * KS);
                if (ks + 1 < KS || v < 15) {
                    const uint4* p = pB + (size_t)nidx * K4STR;
#pragma unroll
                    for (int j = 0; j < NPW; j++) Q[(ks + 1) & 1][j] = p[j * 32];
                }
            }

            // MMA: accumulate into d across ks (fresh at ks==0)
#pragma unroll
            for (int mb = 0; mb < MW; mb++)
#pragma unroll
                for (int p = 0; p < NPW; p++) {
                    float* d0 = &d[(mb * NBW + 2 * p) * 4];
                    float* d1 = &d[(mb * NBW + 2 * p + 1) * 4];
                    const uint4& q = Q[ks & 1][p];
                    if (ks == 0) {
                        mma16816_z(d0, A[mb], q.x, q.y);
                        mma16816_z(d1, A[mb], q.z, q.w);
                    } else {
                        mma16816(d0, A[mb], q.x, q.y);
                        mma16816(d1, A[mb], q.z, q.w);
                    }
                }
        }

        // epilogue once per v: acc += opr[row,v] * d
#pragma unroll
        for (int mb = 0; mb < MW; mb++)
#pragma unroll
            for (int j = 0; j < NBW; j++) {
                float* dd = &d[(mb * NBW + j) * 4];
                float* aa = &acc[(mb * NBW + j) * 4];
                aa[0] = fmaf(o0[mb], dd[0], aa[0]);
                aa[1] = fmaf(o0[mb], dd[1], aa[1]);
                aa[2] = fmaf(o1[mb], dd[2], aa[2]);
                aa[3] = fmaf(o1[mb], dd[3], aa[3]);
            }
    }

    // store: row R = z*D + k
#pragma unroll
    for (int mb = 0; mb < MW; mb++) {
        int R = rbase + moff + mb * 16 + (lane >> 2);
#pragma unroll
        for (int j = 0; j < NBW; j++) {
            int n = (nb0 + j) * 8 + 2 * (lane & 3);
            float* aa = &acc[(mb * NBW + j) * 4];
            if (D == 1) {
                if (R < Z)
                    *(float2*)&out[(size_t)R * 480 + xoff + n] =
                        make_float2(alpha * aa[0], alpha * aa[1]);
                if (R + 8 < Z)
                    *(float2*)&out[(size_t)(R + 8) * 480 + xoff + n] =
                        make_float2(alpha * aa[2], alpha * aa[3]);
            } else {
                if (R < ZD) {
                    int z = R / D, k = R - z * D;
                    out[(size_t)z * 480 + xoff + n * D + k]       = alpha * aa[0];
                    out[(size_t)z * 480 + xoff + (n + 1) * D + k] = alpha * aa[1];
                }
                int R2 = R + 8;
                if (R2 < ZD) {
                    int z = R2 / D, k = R2 - z * D;
                    out[(size_t)z * 480 + xoff + n * D + k]       = alpha * aa[2];
                    out[(size_t)z * 480 + xoff + (n + 1) * D + k] = alpha * aa[3];
                }
            }
        }
    }
}

extern "C" void kernel_launch(void* const* d_in, const int* in_sizes, int n_in,
                              void* d_out, int out_size)
{
    const float* x   = (const float*)d_in[0];
    const float* opr = (const float*)d_in[1];
    const float* w0  = (const float*)d_in[2];
    const float* w1  = (const float*)d_in[3];
    const float* w2  = (const float*)d_in[4];
    float* out = (float*)d_out;

    const int Z = in_sizes[1] / 16;

    const float a0 = 0.022097086912079608f;  // 1/sqrt(128*16)
    const float a1 = 0.03125f;               // 1/sqrt(64*16)
    const float a2 = 0.044194173824159216f;  // 1/sqrt(32*16)

    void *p0, *p1, *p2;
    cudaGetSymbolAddress(&p0, BIMG0);
    cudaGetSymbolAddress(&p1, BIMG1);
    cudaGetSymbolAddress(&p2, BIMG2);

    prepB<128, 128><<<128, 256>>>(w0, (uint4*)p0);
    prepB< 64,  64><<< 32, 256>>>(w1, (uint4*)p1);
    prepB< 32,  32><<<  8, 256>>>(w2, (uint4*)p2);

    // path0: U=128, N=128, D=1; NT=64 (grid.z=2); 256 thr, warps 4x2, m32xn32
    {
        constexpr int SM = 128 * 136 * 2 + 128 * 17 * 4;  // 43520
        cudaFuncSetAttribute(fctp_hmma<128, 128, 64, 1, 4, 2, 2, 4>,
                             cudaFuncAttributeMaxDynamicSharedMemorySize, SM);
        dim3 grid((Z + 127) / 128, 1, 2);
        fctp_hmma<128, 128, 64, 1, 4, 2, 2, 4><<<grid, 256, SM>>>(
            x, opr, (const uint4*)p0, out, Z, 0, a0);
    }
    // path1: U=64, N=64, D=3; NT=64; 256 thr, warps 4x2, m32xn32
    {
        constexpr int SM = 128 * 72 * 2 + 128 * 17 * 4;   // 27136
        cudaFuncSetAttribute(fctp_hmma<64, 64, 64, 3, 4, 2, 2, 4>,
                             cudaFuncAttributeMaxDynamicSharedMemorySize, SM);
        dim3 grid((3 * Z + 127) / 128, 1, 1);
        fctp_hmma<64, 64, 64, 3, 4, 2, 2, 4><<<grid, 256, SM>>>(
            x, opr, (const uint4*)p1, out, Z, 128, a1);
    }
    // path2: U=32, N=32, D=5; NT=32; 256 thr, warps 4x2, m32xn16
    {
        constexpr int SM = 128 * 40 * 2 + 128 * 17 * 4;   // 18944
        cudaFuncSetAttribute(fctp_hmma<32, 32, 32, 5, 4, 2, 2, 2>,
                             cudaFuncAttributeMaxDynamicSharedMemorySize, SM);
        dim3 grid((5 * Z + 127) / 128, 1, 1);
        fctp_hmma<32, 32, 32, 5, 4, 2, 2, 2><<<grid, 256, SM>>>(
            x, opr, (const uint4*)p2, out, Z, 320, a2);
    }
}